// round 5
// baseline (speedup 1.0000x reference)
#include <cuda_runtime.h>
#include <cstdint>

#define NB   1024
#define NT   512
#define NS   64
#define NH   256

// ---------------- packed-weight scratch (allocation-free __device__ globals) -----------
// whP[g][k2][j] = (w_hh[g*256+j][2k2], w_hh[g*256+j][2k2+1])   g in {r,z,n}
__device__ float2 g_whP[3 * 128 * 256];
// wiP[g][k2][j] = (w_ih[g*256+j][2k2], w_ih[g*256+j][2k2+1])
__device__ float2 g_wiP[3 * 32 * 256];
// wbP[k2][j]    = (w_base[j][2k2], w_base[j][2k2+1])
__device__ float2 g_wbP[128 * 256];

// ---------------- f32x2 packed helpers -------------------------------------------------
__device__ __forceinline__ unsigned long long pk2(float a, float b) {
    unsigned long long r;
    asm("mov.b64 %0, {%1,%2};" : "=l"(r)
        : "r"(__float_as_uint(a)), "r"(__float_as_uint(b)));
    return r;
}
__device__ __forceinline__ float2 upk2(unsigned long long v) {
    unsigned int lo, hi;
    asm("mov.b64 {%0,%1}, %2;" : "=r"(lo), "=r"(hi) : "l"(v));
    return make_float2(__uint_as_float(lo), __uint_as_float(hi));
}
__device__ __forceinline__ void ffma2(unsigned long long& d, unsigned long long a,
                                      unsigned long long b) {
    asm("fma.rn.f32x2 %0, %1, %2, %3;" : "=l"(d) : "l"(a), "l"(b), "l"(d));
}

__device__ __forceinline__ float sigmoidf_(float x) { return 1.f / (1.f + __expf(-x)); }
__device__ __forceinline__ float tanhf_(float x) { return 1.f - 2.f / (__expf(2.f * x) + 1.f); }

// ---------------- prep: transpose + k-pair pack weights --------------------------------
__global__ void __launch_bounds__(256) prep_kernel(const float* __restrict__ w_ih,
                                                   const float* __restrict__ w_hh,
                                                   const float* __restrict__ w_base) {
    int idx = blockIdx.x * 256 + threadIdx.x;
    if (idx < 3 * 128 * 256) {
        int g = idx / (128 * 256);
        int rem = idx % (128 * 256);
        int k2 = rem >> 8;
        int j = rem & 255;
        const float* row = w_hh + (size_t)(g * 256 + j) * 256;
        g_whP[idx] = make_float2(row[2 * k2], row[2 * k2 + 1]);
        return;
    }
    int i2 = idx - 3 * 128 * 256;
    if (i2 < 3 * 32 * 256) {
        int g = i2 / (32 * 256);
        int rem = i2 % (32 * 256);
        int k2 = rem >> 8;
        int j = rem & 255;
        const float* row = w_ih + (size_t)(g * 256 + j) * 64;
        g_wiP[i2] = make_float2(row[2 * k2], row[2 * k2 + 1]);
        return;
    }
    int i3 = i2 - 3 * 32 * 256;
    if (i3 < 128 * 256) {
        int k2 = i3 >> 8;
        int j = i3 & 255;
        const float* row = w_base + (size_t)j * 256;
        g_wbP[i3] = make_float2(row[2 * k2], row[2 * k2 + 1]);
    }
}

// ---------------- one dot-step: 3 gate planes x 4 row-pairs x 2 k's = 24 FFMA2 ---------
__device__ __forceinline__ void dot_step(const ulonglong2* __restrict__ hrow,
                                         float2 wr, float2 wz, float2 wn,
                                         unsigned long long* aR, unsigned long long* aZ,
                                         unsigned long long* aN) {
    unsigned long long wrx = pk2(wr.x, wr.x), wry = pk2(wr.y, wr.y);
    unsigned long long wzx = pk2(wz.x, wz.x), wzy = pk2(wz.y, wz.y);
    unsigned long long wnx = pk2(wn.x, wn.x), wny = pk2(wn.y, wn.y);
#pragma unroll
    for (int p = 0; p < 4; p++) {
        ulonglong2 h = hrow[p];  // LDS.128 broadcast: (.x)=rows(b0,b1)@k even, (.y)=@k odd
        ffma2(aR[p], wrx, h.x);
        ffma2(aR[p], wry, h.y);
        ffma2(aZ[p], wzx, h.x);
        ffma2(aZ[p], wzy, h.y);
        ffma2(aN[p], wnx, h.x);
        ffma2(aN[p], wny, h.y);
    }
}

// ---------------- main: 128 CTAs x 256 threads; 8 batch rows per CTA -------------------
__global__ void __launch_bounds__(256, 1) actor_kernel(
    const float* __restrict__ x, const float* __restrict__ b_ih,
    const float* __restrict__ b_hh, const float* __restrict__ b_base,
    const float* __restrict__ w_dir, const float* __restrict__ b_dir,
    const float* __restrict__ w_mag, const float* __restrict__ b_mag,
    float* __restrict__ out) {
    // h state, row-pair packed: hs[k2][p].x = (h[2p][2k2], h[2p+1][2k2]) ; .y = k odd
    __shared__ ulonglong2 hs[128][4];
    __shared__ ulonglong2 xs[32][4];
    __shared__ float hb[8][256];

    const int tid = threadIdx.x;          // tid = gate-dim j in [0,256)
    const int bbase = blockIdx.x * 8;

    // zero h state
    {
        unsigned long long* hz = (unsigned long long*)hs;
        hz[tid] = 0ULL;
        hz[tid + 256] = 0ULL;
        hz[tid + 512] = 0ULL;
        hz[tid + 768] = 0ULL;
    }

    const float br = b_ih[tid] + b_hh[tid];
    const float bz = b_ih[256 + tid] + b_hh[256 + tid];
    const float bin = b_ih[512 + tid];
    const float bhn = b_hh[512 + tid];

    float hreg[8];
#pragma unroll
    for (int i = 0; i < 8; i++) hreg[i] = 0.f;

    unsigned long long aR[4], aZ[4], aNi[4], aNh[4];
#pragma unroll
    for (int p = 0; p < 4; p++) { aR[p] = aZ[p] = aNi[p] = aNh[p] = 0ULL; }

    const float2* __restrict__ wiR = g_wiP;
    const float2* __restrict__ wiZ = g_wiP + 32 * 256;
    const float2* __restrict__ wiN = g_wiP + 2 * 32 * 256;
    const float2* __restrict__ whR = g_whP;
    const float2* __restrict__ whZ = g_whP + 128 * 256;
    const float2* __restrict__ whN = g_whP + 2 * 128 * 256;

    for (int t = 0; t < NT; ++t) {
        // stage x_t for 8 rows into row-pair-packed layout
        if (tid < 128) {
            int row = tid >> 4, c = tid & 15;
            const float4 v =
                *(const float4*)(x + ((size_t)(bbase + row) * NT + t) * NS + c * 4);
            float* xf = (float*)xs;
            int p = row >> 1, s = row & 1;
            int base0 = (2 * c) * 16 + p * 4 + s;
            xf[base0] = v.x;
            xf[base0 + 2] = v.y;
            xf[base0 + 16] = v.z;
            xf[base0 + 18] = v.w;
        }
        __syncthreads();  // x staged; h from previous step visible

        // input contribution: gi_r/z -> aR/aZ, gi_n -> aNi
#pragma unroll 4
        for (int k2 = 0; k2 < 32; ++k2) {
            float2 wr = wiR[k2 * 256 + tid];
            float2 wz = wiZ[k2 * 256 + tid];
            float2 wn = wiN[k2 * 256 + tid];
            dot_step(&xs[k2][0], wr, wz, wn, aR, aZ, aNi);
        }
        // recurrent contribution: gh_r/z -> aR/aZ, gh_n -> aNh
#pragma unroll 4
        for (int k2 = 0; k2 < 128; ++k2) {
            float2 wr = whR[k2 * 256 + tid];
            float2 wz = whZ[k2 * 256 + tid];
            float2 wn = whN[k2 * 256 + tid];
            dot_step(&hs[k2][0], wr, wz, wn, aR, aZ, aNh);
        }

        // gate math (thread-local: thread j owns h[*][j])
        float hnew[8];
#pragma unroll
        for (int p = 0; p < 4; p++) {
            float2 rv = upk2(aR[p]), zv = upk2(aZ[p]);
            float2 niv = upk2(aNi[p]), nhv = upk2(aNh[p]);
            {
                float r = sigmoidf_(rv.x + br);
                float z = sigmoidf_(zv.x + bz);
                float n = tanhf_(niv.x + bin + r * (nhv.x + bhn));
                hnew[2 * p] = (1.f - z) * n + z * hreg[2 * p];
            }
            {
                float r = sigmoidf_(rv.y + br);
                float z = sigmoidf_(zv.y + bz);
                float n = tanhf_(niv.y + bin + r * (nhv.y + bhn));
                hnew[2 * p + 1] = (1.f - z) * n + z * hreg[2 * p + 1];
            }
            aR[p] = aZ[p] = aNi[p] = aNh[p] = 0ULL;
        }
#pragma unroll
        for (int i = 0; i < 8; i++) hreg[i] = hnew[i];

        __syncthreads();  // everyone done READING hs before we overwrite
#pragma unroll
        for (int p = 0; p < 4; p++) {
            unsigned long long hv = pk2(hreg[2 * p], hreg[2 * p + 1]);
            ((unsigned long long*)&hs[tid >> 1][p])[tid & 1] = hv;
        }
    }
    __syncthreads();  // final h visible

    // base layer: hb[b][j] = relu(h . w_base[j] + b_base[j])
    unsigned long long aB[4];
#pragma unroll
    for (int p = 0; p < 4; p++) aB[p] = 0ULL;
#pragma unroll 4
    for (int k2 = 0; k2 < 128; ++k2) {
        float2 wb = g_wbP[k2 * 256 + tid];
        unsigned long long wbx = pk2(wb.x, wb.x), wby = pk2(wb.y, wb.y);
#pragma unroll
        for (int p = 0; p < 4; p++) {
            ulonglong2 h = hs[k2][p];
            ffma2(aB[p], wbx, h.x);
            ffma2(aB[p], wby, h.y);
        }
    }
    {
        float bb = b_base[tid];
#pragma unroll
        for (int p = 0; p < 4; p++) {
            float2 v = upk2(aB[p]);
            hb[2 * p][tid] = fmaxf(v.x + bb, 0.f);
            hb[2 * p + 1][tid] = fmaxf(v.y + bb, 0.f);
        }
    }
    __syncthreads();

    // factorized heads: 64 outputs per CTA
    if (tid < 64) {
        int b = tid >> 3, a = tid & 7;
        float aD = b_dir[a], aM = b_mag[a];
        const float* __restrict__ wd = w_dir + a * 256;
        const float* __restrict__ wm = w_mag + a * 256;
#pragma unroll 4
        for (int k = 0; k < 256; ++k) {
            float hv = hb[b][k];
            aD = fmaf(wd[k], hv, aD);
            aM = fmaf(wm[k], hv, aM);
        }
        float d = tanhf_(aD);
        float m = sigmoidf_(aM);
        out[(size_t)(bbase + b) * 8 + a] = d * m;
    }
}

// ---------------- launch ----------------------------------------------------------------
extern "C" void kernel_launch(void* const* d_in, const int* in_sizes, int n_in,
                              void* d_out, int out_size) {
    const float* x      = (const float*)d_in[0];
    const float* w_ih   = (const float*)d_in[1];
    const float* w_hh   = (const float*)d_in[2];
    const float* b_ih   = (const float*)d_in[3];
    const float* b_hh   = (const float*)d_in[4];
    const float* w_base = (const float*)d_in[5];
    // d_in[6] = b_base, d_in[7] = w_dir, d_in[8] = b_dir, d_in[9] = w_mag, d_in[10] = b_mag
    const float* b_base = (const float*)d_in[6];
    const float* w_dir  = (const float*)d_in[7];
    const float* b_dir  = (const float*)d_in[8];
    const float* w_mag  = (const float*)d_in[9];
    const float* b_mag  = (const float*)d_in[10];

    // (3*128*256 + 3*32*256 + 128*256) / 256 = 608 blocks exactly
    prep_kernel<<<608, 256>>>(w_ih, w_hh, w_base);
    actor_kernel<<<128, 256>>>(x, b_ih, b_hh, b_base, w_dir, b_dir, w_mag, b_mag,
                               (float*)d_out);
}